// round 9
// baseline (speedup 1.0000x reference)
#include <cuda_runtime.h>
#include <cuda_bf16.h>
#include <cstdint>

// ============================================================================
// Problem constants
// ============================================================================
#define NB     16384
#define NNODE  12
#define CDIM   512
#define ROWS   (NB * NNODE)
#define KDIM   1024
#define NDIM   512
#define TOPK   4
#define BN_EPS 1e-5f

// ============================================================================
// Helpers (baseline PTX only)
// ============================================================================
__device__ __forceinline__ uint32_t smem_u32(const void* p) {
    uint32_t a;
    asm("{ .reg .u64 t; cvta.to.shared.u64 t, %1; cvt.u32.u64 %0, t; }" : "=r"(a) : "l"(p));
    return a;
}
__device__ __forceinline__ void ldsm_x4(uint32_t* r, uint32_t addr) {
    asm volatile("ldmatrix.sync.aligned.m8n8.x4.shared.b16 {%0,%1,%2,%3}, [%4];"
                 : "=r"(r[0]), "=r"(r[1]), "=r"(r[2]), "=r"(r[3]) : "r"(addr));
}
__device__ __forceinline__ void cp_async16(uint32_t saddr, const void* gaddr) {
    asm volatile("cp.async.cg.shared.global [%0], [%1], 16;" :: "r"(saddr), "l"(gaddr));
}
#define CP_COMMIT() asm volatile("cp.async.commit_group;" ::: "memory")
#define CP_WAIT0()  asm volatile("cp.async.wait_group 0;" ::: "memory")

__device__ __forceinline__ void mma_bf16(float* d, const uint32_t* a, const uint32_t* b) {
    asm volatile(
        "mma.sync.aligned.m16n8k16.row.col.f32.bf16.bf16.f32 "
        "{%0,%1,%2,%3}, {%4,%5,%6,%7}, {%8,%9}, {%0,%1,%2,%3};"
        : "+f"(d[0]), "+f"(d[1]), "+f"(d[2]), "+f"(d[3])
        : "r"(a[0]), "r"(a[1]), "r"(a[2]), "r"(a[3]), "r"(b[0]), "r"(b[1]));
}
__device__ __forceinline__ uint32_t pack_hi2(float a, float b) {
    __nv_bfloat162 t;
    t.x = __float2bfloat16(a);
    t.y = __float2bfloat16(b);
    return *reinterpret_cast<uint32_t*>(&t);
}
__device__ __forceinline__ uint32_t pack_lo2(float a, float b) {
    __nv_bfloat162 t;
    __nv_bfloat16 ha = __float2bfloat16(a);
    __nv_bfloat16 hb = __float2bfloat16(b);
    t.x = __float2bfloat16(a - __bfloat162float(ha));
    t.y = __float2bfloat16(b - __bfloat162float(hb));
    return *reinterpret_cast<uint32_t*>(&t);
}

// ============================================================================
// Device scratch
// ============================================================================
__device__ __align__(16) __nv_bfloat16 g_ahi[(size_t)ROWS * KDIM];
__device__ __align__(16) __nv_bfloat16 g_alo[(size_t)ROWS * KDIM];
__device__ __align__(16) __nv_bfloat16 g_whi[(size_t)NDIM * KDIM];
__device__ __align__(16) __nv_bfloat16 g_wlo[(size_t)NDIM * KDIM];
__device__ __align__(16) float g_h[(size_t)ROWS * CDIM];
__device__ float g_rs[ROWS];
__device__ float g_sum[NNODE];
__device__ float g_sumsq[NNODE];
__device__ float g_scale[NNODE];
__device__ float g_shift[NNODE];

// ============================================================================
// Kernel 0a
// ============================================================================
__global__ void k_zero_stats() {
    int t = threadIdx.x;
    if (t < NNODE) { g_sum[t] = 0.f; g_sumsq[t] = 0.f; }
}

// ============================================================================
// Kernel 0b: pack W = [Vw | Uw] as bf16 hi/lo
// ============================================================================
__global__ void k_prep_w(const float* __restrict__ Uw, const float* __restrict__ Vw) {
    int idx = blockIdx.x * blockDim.x + threadIdx.x;
    if (idx >= NDIM * KDIM) return;
    int d = idx >> 10;
    int k = idx & 1023;
    float v = (k < 512) ? Vw[d * 512 + k] : Uw[d * 512 + (k - 512)];
    __nv_bfloat16 hi = __float2bfloat16(v);
    float lo = v - __bfloat162float(hi);
    g_whi[idx] = hi;
    g_wlo[idx] = __float2bfloat16(lo);
}

// ============================================================================
// Kernel 1: adjacency + aggregation -> A-operand rows [y | x] (hi/lo)
// ============================================================================
__global__ __launch_bounds__(128) void k_adjacency(const float* __restrict__ x) {
    __shared__ __align__(16) float sx[NNODE][CDIM];
    __shared__ float ssim[NNODE][NNODE];
    __shared__ float sA[NNODE][NNODE];
    __shared__ float sthr[NNODE];
    __shared__ float sdinv[NNODE];

    const int tid = threadIdx.x;
    const int b   = blockIdx.x;

    {
        const float4* src = reinterpret_cast<const float4*>(x + (size_t)b * NNODE * CDIM);
        float4* dst = reinterpret_cast<float4*>(&sx[0][0]);
        for (int i = tid; i < NNODE * CDIM / 4; i += 128) dst[i] = src[i];
    }
    __syncthreads();

    if (tid < 78) {
        int i = 0, t = tid;
        while (t >= NNODE - i) { t -= NNODE - i; i++; }
        int j = i + t;
        float a0 = 0.f, a1 = 0.f, a2 = 0.f, a3 = 0.f;
        #pragma unroll 4
        for (int c = 0; c < CDIM; c += 4) {
            float4 a  = *reinterpret_cast<const float4*>(&sx[i][c]);
            float4 bb = *reinterpret_cast<const float4*>(&sx[j][c]);
            a0 += a.x * bb.x; a1 += a.y * bb.y;
            a2 += a.z * bb.z; a3 += a.w * bb.w;
        }
        float acc = (a0 + a1) + (a2 + a3);
        ssim[i][j] = acc;
        ssim[j][i] = acc;
    }
    __syncthreads();

    if (tid < NNODE) {
        float v[NNODE];
        #pragma unroll
        for (int j = 0; j < NNODE; j++) v[j] = ssim[tid][j];
        float thr = 0.f;
        #pragma unroll
        for (int t = 0; t < TOPK; t++) {
            int m = 0;
            float mv = v[0];
            #pragma unroll
            for (int j = 1; j < NNODE; j++) if (v[j] > mv) { mv = v[j]; m = j; }
            thr = mv;
            v[m] = -3.4e38f;
        }
        sthr[tid] = thr;
        int deg = 0;
        #pragma unroll
        for (int j = 0; j < NNODE; j++) deg += (ssim[tid][j] >= thr) ? 1 : 0;
        sdinv[tid] = rsqrtf((float)deg);
    }
    __syncthreads();

    for (int t = tid; t < NNODE * NNODE; t += 128) {   // 144 > 128: grid-stride
        int i = t / NNODE, j = t % NNODE;
        float adj = (ssim[i][j] >= sthr[i]) ? 1.f : 0.f;
        sA[i][j] = sdinv[i] * sdinv[j] * adj;
    }
    __syncthreads();

    if (tid < NNODE) {
        float rs = 0.f;
        #pragma unroll
        for (int j = 0; j < NNODE; j++) rs += sA[tid][j];
        g_rs[(size_t)b * NNODE + tid] = rs;
    }

    // y = A @ x -> cols [0,512)
    {
        const int c0 = tid * 4;
        float4 xv[NNODE];
        #pragma unroll
        for (int j = 0; j < NNODE; j++)
            xv[j] = *reinterpret_cast<const float4*>(&sx[j][c0]);
        #pragma unroll
        for (int i = 0; i < NNODE; i++) {
            float a0 = 0.f, a1 = 0.f, a2 = 0.f, a3 = 0.f;
            #pragma unroll
            for (int j = 0; j < NNODE; j++) {
                float w = sA[i][j];
                a0 += w * xv[j].x; a1 += w * xv[j].y;
                a2 += w * xv[j].z; a3 += w * xv[j].w;
            }
            size_t o = ((size_t)b * NNODE + i) * KDIM + c0;
            uint2 hi = make_uint2(pack_hi2(a0, a1), pack_hi2(a2, a3));
            uint2 lo = make_uint2(pack_lo2(a0, a1), pack_lo2(a2, a3));
            *reinterpret_cast<uint2*>(g_ahi + o) = hi;
            *reinterpret_cast<uint2*>(g_alo + o) = lo;
        }
    }

    // x -> cols [512,1024)
    for (int u = tid; u < NNODE * 128; u += 128) {
        int i = u >> 7, q = u & 127;
        float4 v = *reinterpret_cast<const float4*>(&sx[i][q * 4]);
        size_t o = ((size_t)b * NNODE + i) * KDIM + 512 + q * 4;
        uint2 hi = make_uint2(pack_hi2(v.x, v.y), pack_hi2(v.z, v.w));
        uint2 lo = make_uint2(pack_lo2(v.x, v.y), pack_lo2(v.z, v.w));
        *reinterpret_cast<uint2*>(g_ahi + o) = hi;
        *reinterpret_cast<uint2*>(g_alo + o) = lo;
    }
}

// ============================================================================
// Kernel 2: GEMM  h = [y|x] @ Wcat^T + rs*Vb + Ub   (bf16x3, HMMA)
// BM=128, BN=128, BK=32, 256 thr, 2-stage cp.async, 2 CTAs/SM,
// ONE __syncthreads per chunk, B fragments via ldsm_x4.
// ============================================================================
#define LDA        40
#define TILE_B     (128 * LDA)
#define STAGE_E    (4 * TILE_B)
#define STAGE_BYTES (STAGE_E * 2)          // 40960
#define SMEM2_BYTES (2 * STAGE_BYTES)      // 81920

__device__ __forceinline__ void issue_chunk(uint32_t sbase, int mrow0, int n0,
                                            int kc, int arow, int acol) {
    const size_t ga = (size_t)(mrow0 + arow) * KDIM + kc * 32 + acol;
    const size_t gw = (size_t)(n0 + arow) * KDIM + kc * 32 + acol;
    const uint32_t off = (uint32_t)(arow * LDA + acol) * 2;
    cp_async16(sbase + off,                     g_ahi + ga);
    cp_async16(sbase + off + 16,                g_ahi + ga + 8);
    cp_async16(sbase + TILE_B * 2 + off,        g_alo + ga);
    cp_async16(sbase + TILE_B * 2 + off + 16,   g_alo + ga + 8);
    cp_async16(sbase + 2 * TILE_B * 2 + off,      g_whi + gw);
    cp_async16(sbase + 2 * TILE_B * 2 + off + 16, g_whi + gw + 8);
    cp_async16(sbase + 3 * TILE_B * 2 + off,      g_wlo + gw);
    cp_async16(sbase + 3 * TILE_B * 2 + off + 16, g_wlo + gw + 8);
}

__global__ __launch_bounds__(256, 2) void k_gemm(const float* __restrict__ Vb,
                                                 const float* __restrict__ Ub) {
    extern __shared__ __align__(128) __nv_bfloat16 sm[];
    __shared__ float sBias[256];
    __shared__ float sred[24];

    const int tid  = threadIdx.x;
    const int wid  = tid >> 5;
    const int lane = tid & 31;

    const int ntile = blockIdx.x & 3;
    const int mtile = blockIdx.x >> 2;
    const int mrow0 = mtile * 128;
    const int n0    = ntile * 128;

    const int wm = (wid & 3) * 32;
    const int wn = (wid >> 2) * 64;

    for (int i = tid; i < 128; i += 256) {
        sBias[i]       = Vb[n0 + i];
        sBias[128 + i] = Ub[n0 + i];
    }
    if (tid < 24) sred[tid] = 0.f;

    float acc[2][8][4];
    #pragma unroll
    for (int mi = 0; mi < 2; mi++)
        #pragma unroll
        for (int nb = 0; nb < 8; nb++)
            #pragma unroll
            for (int q = 0; q < 4; q++) acc[mi][nb][q] = 0.f;

    const int arow = tid >> 1;
    const int acol = (tid & 1) * 16;
    const uint32_t sm_addr = smem_u32(sm);

    // prologue: chunk 0 into stage 0
    issue_chunk(sm_addr, mrow0, n0, 0, arow, acol);
    CP_COMMIT();

    #pragma unroll 1
    for (int kc = 0; kc < 32; kc++) {
        CP_WAIT0();              // chunk kc resident
        __syncthreads();         // ...visible to all; prev compute also fenced

        // issue chunk kc+1 into stage (kc+1)&1 (freed by prev iter's compute)
        const int kn = kc + 1;
        if (kn < 32) {
            issue_chunk(sm_addr + (uint32_t)(kn & 1) * STAGE_BYTES, mrow0, n0, kn, arow, acol);
            CP_COMMIT();
        }

        // ---- compute on stage kc&1 ----
        const uint32_t sA_hi = sm_addr + (uint32_t)(kc & 1) * STAGE_BYTES;
        const uint32_t sA_lo = sA_hi + TILE_B * 2;
        const uint32_t sB_hi = sA_hi + 2 * TILE_B * 2;
        const uint32_t sB_lo = sA_hi + 3 * TILE_B * 2;

        #pragma unroll
        for (int ks = 0; ks < 2; ks++) {
            const int k0 = ks * 16;
            uint32_t aH[2][4], aL[2][4];
            const int afr = lane & 15;
            const int afc = k0 + (lane >> 4) * 8;
            #pragma unroll
            for (int mi = 0; mi < 2; mi++) {
                uint32_t ad = (uint32_t)((wm + mi * 16 + afr) * LDA + afc) * 2;
                ldsm_x4(aH[mi], sA_hi + ad);
                ldsm_x4(aL[mi], sA_lo + ad);
            }
            #pragma unroll
            for (int g = 0; g < 2; g++) {
                // B fragments for 4 nb via 2 ldsm_x4 per hi/lo:
                // quad = lane>>3: (quad>>1) selects nb within pair, (quad&1) selects k-half
                uint32_t bH[4][2], bL[4][2];
                const int quad = lane >> 3;
                const int rsel = (quad >> 1) * 8 + (lane & 7);
                const int csel = k0 + (quad & 1) * 8;
                #pragma unroll
                for (int np = 0; np < 2; np++) {
                    const int brow = wn + (g * 4 + np * 2) * 8 + rsel;
                    uint32_t bd = (uint32_t)(brow * LDA + csel) * 2;
                    uint32_t r[4];
                    ldsm_x4(r, sB_hi + bd);
                    bH[np*2][0] = r[0]; bH[np*2][1] = r[1];
                    bH[np*2+1][0] = r[2]; bH[np*2+1][1] = r[3];
                    ldsm_x4(r, sB_lo + bd);
                    bL[np*2][0] = r[0]; bL[np*2][1] = r[1];
                    bL[np*2+1][0] = r[2]; bL[np*2+1][1] = r[3];
                }
                // term-major MMA issue (no RAW chains on same accumulator)
                #pragma unroll
                for (int nq = 0; nq < 4; nq++)
                    #pragma unroll
                    for (int mi = 0; mi < 2; mi++)
                        mma_bf16(acc[mi][g * 4 + nq], aH[mi], bH[nq]);
                #pragma unroll
                for (int nq = 0; nq < 4; nq++)
                    #pragma unroll
                    for (int mi = 0; mi < 2; mi++)
                        mma_bf16(acc[mi][g * 4 + nq], aL[mi], bH[nq]);
                #pragma unroll
                for (int nq = 0; nq < 4; nq++)
                    #pragma unroll
                    for (int mi = 0; mi < 2; mi++)
                        mma_bf16(acc[mi][g * 4 + nq], aH[mi], bL[nq]);
            }
        }
    }

    // ---- epilogue: bias + write h + fused BN stats ----
    const int l4 = lane >> 2;
    const int lc = (lane & 3) * 2;

    #pragma unroll
    for (int mi = 0; mi < 2; mi++) {
        #pragma unroll
        for (int rr = 0; rr < 2; rr++) {
            const int row = wm + mi * 16 + rr * 8 + l4;
            const size_t grow = (size_t)mrow0 + row;
            const float rsv = g_rs[grow];
            float* hrow = g_h + grow * CDIM + n0;
            float lsum = 0.f, lsq = 0.f;
            #pragma unroll
            for (int nb = 0; nb < 8; nb++) {
                const int c = wn + nb * 8 + lc;
                float v0 = acc[mi][nb][rr * 2 + 0] + rsv * sBias[c]     + sBias[128 + c];
                float v1 = acc[mi][nb][rr * 2 + 1] + rsv * sBias[c + 1] + sBias[128 + c + 1];
                lsum += v0 + v1;
                lsq  += v0 * v0 + v1 * v1;
                *reinterpret_cast<float2*>(hrow + c) = make_float2(v0, v1);
            }
            lsum += __shfl_xor_sync(0xFFFFFFFF, lsum, 1);
            lsq  += __shfl_xor_sync(0xFFFFFFFF, lsq, 1);
            lsum += __shfl_xor_sync(0xFFFFFFFF, lsum, 2);
            lsq  += __shfl_xor_sync(0xFFFFFFFF, lsq, 2);
            if ((lane & 3) == 0) {
                int node = (int)(grow % NNODE);
                atomicAdd(&sred[node], lsum);
                atomicAdd(&sred[12 + node], lsq);
            }
        }
    }
    __syncthreads();
    if (tid < NNODE) {
        atomicAdd(&g_sum[tid], sred[tid]);
        atomicAdd(&g_sumsq[tid], sred[12 + tid]);
    }
}

// ============================================================================
// Kernel 3: finalize BN stats
// ============================================================================
__global__ void k_finalize(const float* __restrict__ gamma, const float* __restrict__ beta) {
    int t = threadIdx.x;
    if (t < NNODE) {
        const float inv_n = 1.0f / ((float)NB * (float)CDIM);
        float mean = g_sum[t] * inv_n;
        float var  = g_sumsq[t] * inv_n - mean * mean;
        var = fmaxf(var, 0.f);
        float sc = gamma[t] * rsqrtf(var + BN_EPS);
        g_scale[t] = sc;
        g_shift[t] = beta[t] - mean * sc;
    }
}

// ============================================================================
// Kernel 4: out = relu(x + h*scale + shift)   (2 float4 per thread)
// ============================================================================
__global__ __launch_bounds__(512) void k_output(const float* __restrict__ x,
                                                float* __restrict__ out) {
    const size_t base = (size_t)blockIdx.x * 1024 + threadIdx.x;
    #pragma unroll
    for (int r = 0; r < 2; r++) {
        size_t idx = base + r * 512;
        const float4 xv = reinterpret_cast<const float4*>(x)[idx];
        const float4 hv = reinterpret_cast<const float4*>(g_h)[idx];
        int node = (int)((idx >> 7) % NNODE);
        float sc = g_scale[node], sh = g_shift[node];
        float4 o;
        o.x = fmaxf(fmaf(hv.x, sc, sh) + xv.x, 0.f);
        o.y = fmaxf(fmaf(hv.y, sc, sh) + xv.y, 0.f);
        o.z = fmaxf(fmaf(hv.z, sc, sh) + xv.z, 0.f);
        o.w = fmaxf(fmaf(hv.w, sc, sh) + xv.w, 0.f);
        reinterpret_cast<float4*>(out)[idx] = o;
    }
}

// ============================================================================
// Launch
// ============================================================================
extern "C" void kernel_launch(void* const* d_in, const int* in_sizes, int n_in,
                              void* d_out, int out_size) {
    const float* x     = (const float*)d_in[0];
    const float* Uw    = (const float*)d_in[1];
    const float* Ub    = (const float*)d_in[2];
    const float* Vw    = (const float*)d_in[3];
    const float* Vb    = (const float*)d_in[4];
    const float* gamma = (const float*)d_in[5];
    const float* beta  = (const float*)d_in[6];
    float* out = (float*)d_out;

    cudaFuncSetAttribute(k_gemm, cudaFuncAttributeMaxDynamicSharedMemorySize, SMEM2_BYTES);

    k_zero_stats<<<1, 32>>>();
    k_prep_w<<<(NDIM * KDIM + 255) / 256, 256>>>(Uw, Vw);
    k_adjacency<<<NB, 128>>>(x);
    k_gemm<<<(ROWS / 128) * 4, 256, SMEM2_BYTES>>>(Vb, Ub);
    k_finalize<<<1, 32>>>(gamma, beta);
    k_output<<<(unsigned)((size_t)ROWS * CDIM / 4 / 1024), 512>>>(x, out);
}

// round 10
// speedup vs baseline: 1.7760x; 1.7760x over previous
#include <cuda_runtime.h>
#include <cuda_bf16.h>
#include <cstdint>

// ============================================================================
// Problem constants
// ============================================================================
#define NB     16384
#define NNODE  12
#define CDIM   512
#define SXLD   (CDIM + 4)      // padded smem row: 516 floats (bank-conflict fix)
#define ROWS   (NB * NNODE)
#define KDIM   1024
#define NDIM   512
#define TOPK   4
#define BN_EPS 1e-5f

// ============================================================================
// Helpers (baseline PTX only)
// ============================================================================
__device__ __forceinline__ uint32_t smem_u32(const void* p) {
    uint32_t a;
    asm("{ .reg .u64 t; cvta.to.shared.u64 t, %1; cvt.u32.u64 %0, t; }" : "=r"(a) : "l"(p));
    return a;
}
__device__ __forceinline__ void ldsm_x4(uint32_t* r, uint32_t addr) {
    asm volatile("ldmatrix.sync.aligned.m8n8.x4.shared.b16 {%0,%1,%2,%3}, [%4];"
                 : "=r"(r[0]), "=r"(r[1]), "=r"(r[2]), "=r"(r[3]) : "r"(addr));
}
__device__ __forceinline__ void ldsm_x2(uint32_t* r, uint32_t addr) {
    asm volatile("ldmatrix.sync.aligned.m8n8.x2.shared.b16 {%0,%1}, [%2];"
                 : "=r"(r[0]), "=r"(r[1]) : "r"(addr));
}
__device__ __forceinline__ void cp_async16(uint32_t saddr, const void* gaddr) {
    asm volatile("cp.async.cg.shared.global [%0], [%1], 16;" :: "r"(saddr), "l"(gaddr));
}
#define CP_COMMIT() asm volatile("cp.async.commit_group;" ::: "memory")
#define CP_WAIT1()  asm volatile("cp.async.wait_group 1;" ::: "memory")

__device__ __forceinline__ void mma_bf16(float* d, const uint32_t* a, const uint32_t* b) {
    asm volatile(
        "mma.sync.aligned.m16n8k16.row.col.f32.bf16.bf16.f32 "
        "{%0,%1,%2,%3}, {%4,%5,%6,%7}, {%8,%9}, {%0,%1,%2,%3};"
        : "+f"(d[0]), "+f"(d[1]), "+f"(d[2]), "+f"(d[3])
        : "r"(a[0]), "r"(a[1]), "r"(a[2]), "r"(a[3]), "r"(b[0]), "r"(b[1]));
}
__device__ __forceinline__ uint32_t pack_hi2(float a, float b) {
    __nv_bfloat162 t;
    t.x = __float2bfloat16(a);
    t.y = __float2bfloat16(b);
    return *reinterpret_cast<uint32_t*>(&t);
}
__device__ __forceinline__ uint32_t pack_lo2(float a, float b) {
    __nv_bfloat162 t;
    __nv_bfloat16 ha = __float2bfloat16(a);
    __nv_bfloat16 hb = __float2bfloat16(b);
    t.x = __float2bfloat16(a - __bfloat162float(ha));
    t.y = __float2bfloat16(b - __bfloat162float(hb));
    return *reinterpret_cast<uint32_t*>(&t);
}

// ============================================================================
// Device scratch
// ============================================================================
__device__ __align__(16) __nv_bfloat16 g_ahi[(size_t)ROWS * KDIM];
__device__ __align__(16) __nv_bfloat16 g_alo[(size_t)ROWS * KDIM];
__device__ __align__(16) __nv_bfloat16 g_whi[(size_t)NDIM * KDIM];
__device__ __align__(16) __nv_bfloat16 g_wlo[(size_t)NDIM * KDIM];
__device__ __align__(16) float g_h[(size_t)ROWS * CDIM];
__device__ float g_rs[ROWS];
__device__ float g_sum[NNODE];
__device__ float g_sumsq[NNODE];
__device__ float g_scale[NNODE];
__device__ float g_shift[NNODE];

// ============================================================================
// Kernel 0a
// ============================================================================
__global__ void k_zero_stats() {
    int t = threadIdx.x;
    if (t < NNODE) { g_sum[t] = 0.f; g_sumsq[t] = 0.f; }
}

// ============================================================================
// Kernel 0b: pack W = [Vw | Uw] as bf16 hi/lo
// ============================================================================
__global__ void k_prep_w(const float* __restrict__ Uw, const float* __restrict__ Vw) {
    int idx = blockIdx.x * blockDim.x + threadIdx.x;
    if (idx >= NDIM * KDIM) return;
    int d = idx >> 10;
    int k = idx & 1023;
    float v = (k < 512) ? Vw[d * 512 + k] : Uw[d * 512 + (k - 512)];
    __nv_bfloat16 hi = __float2bfloat16(v);
    float lo = v - __bfloat162float(hi);
    g_whi[idx] = hi;
    g_wlo[idx] = __float2bfloat16(lo);
}

// ============================================================================
// Kernel 1: adjacency + aggregation -> A-operand rows [y | x] (hi/lo)
// sx padded to 516 floats/row: the sim-dot phase previously had all threads
// hitting one bank column (row stride 2048B). 516 = 4 mod 32 spreads banks.
// ============================================================================
__global__ __launch_bounds__(128) void k_adjacency(const float* __restrict__ x) {
    __shared__ __align__(16) float sx[NNODE][SXLD];
    __shared__ float ssim[NNODE][NNODE];
    __shared__ float sA[NNODE][NNODE];
    __shared__ float sthr[NNODE];
    __shared__ float sdinv[NNODE];

    const int tid = threadIdx.x;
    const int b   = blockIdx.x;

    // load x[b] rows into padded smem
    {
        const float4* src = reinterpret_cast<const float4*>(x + (size_t)b * NNODE * CDIM);
        for (int u = tid; u < NNODE * CDIM / 4; u += 128) {
            int i = u >> 7;           // row (128 float4 per row)
            int q = u & 127;          // float4 within row
            *reinterpret_cast<float4*>(&sx[i][q * 4]) = src[u];
        }
    }
    __syncthreads();

    if (tid < 78) {
        int i = 0, t = tid;
        while (t >= NNODE - i) { t -= NNODE - i; i++; }
        int j = i + t;
        float a0 = 0.f, a1 = 0.f, a2 = 0.f, a3 = 0.f;
        #pragma unroll 4
        for (int c = 0; c < CDIM; c += 4) {
            float4 a  = *reinterpret_cast<const float4*>(&sx[i][c]);
            float4 bb = *reinterpret_cast<const float4*>(&sx[j][c]);
            a0 += a.x * bb.x; a1 += a.y * bb.y;
            a2 += a.z * bb.z; a3 += a.w * bb.w;
        }
        float acc = (a0 + a1) + (a2 + a3);
        ssim[i][j] = acc;
        ssim[j][i] = acc;
    }
    __syncthreads();

    if (tid < NNODE) {
        float v[NNODE];
        #pragma unroll
        for (int j = 0; j < NNODE; j++) v[j] = ssim[tid][j];
        float thr = 0.f;
        #pragma unroll
        for (int t = 0; t < TOPK; t++) {
            int m = 0;
            float mv = v[0];
            #pragma unroll
            for (int j = 1; j < NNODE; j++) if (v[j] > mv) { mv = v[j]; m = j; }
            thr = mv;
            v[m] = -3.4e38f;
        }
        sthr[tid] = thr;
        int deg = 0;
        #pragma unroll
        for (int j = 0; j < NNODE; j++) deg += (ssim[tid][j] >= thr) ? 1 : 0;
        sdinv[tid] = rsqrtf((float)deg);
    }
    __syncthreads();

    for (int t = tid; t < NNODE * NNODE; t += 128) {   // 144 > 128: grid-stride
        int i = t / NNODE, j = t % NNODE;
        float adj = (ssim[i][j] >= sthr[i]) ? 1.f : 0.f;
        sA[i][j] = sdinv[i] * sdinv[j] * adj;
    }
    __syncthreads();

    if (tid < NNODE) {
        float rs = 0.f;
        #pragma unroll
        for (int j = 0; j < NNODE; j++) rs += sA[tid][j];
        g_rs[(size_t)b * NNODE + tid] = rs;
    }

    // y = A @ x -> cols [0,512)
    {
        const int c0 = tid * 4;
        float4 xv[NNODE];
        #pragma unroll
        for (int j = 0; j < NNODE; j++)
            xv[j] = *reinterpret_cast<const float4*>(&sx[j][c0]);
        #pragma unroll
        for (int i = 0; i < NNODE; i++) {
            float a0 = 0.f, a1 = 0.f, a2 = 0.f, a3 = 0.f;
            #pragma unroll
            for (int j = 0; j < NNODE; j++) {
                float w = sA[i][j];
                a0 += w * xv[j].x; a1 += w * xv[j].y;
                a2 += w * xv[j].z; a3 += w * xv[j].w;
            }
            size_t o = ((size_t)b * NNODE + i) * KDIM + c0;
            uint2 hi = make_uint2(pack_hi2(a0, a1), pack_hi2(a2, a3));
            uint2 lo = make_uint2(pack_lo2(a0, a1), pack_lo2(a2, a3));
            *reinterpret_cast<uint2*>(g_ahi + o) = hi;
            *reinterpret_cast<uint2*>(g_alo + o) = lo;
        }
    }

    // x -> cols [512,1024)
    for (int u = tid; u < NNODE * 128; u += 128) {
        int i = u >> 7, q = u & 127;
        float4 v = *reinterpret_cast<const float4*>(&sx[i][q * 4]);
        size_t o = ((size_t)b * NNODE + i) * KDIM + 512 + q * 4;
        uint2 hi = make_uint2(pack_hi2(v.x, v.y), pack_hi2(v.z, v.w));
        uint2 lo = make_uint2(pack_lo2(v.x, v.y), pack_lo2(v.z, v.w));
        *reinterpret_cast<uint2*>(g_ahi + o) = hi;
        *reinterpret_cast<uint2*>(g_alo + o) = lo;
    }
}

// ============================================================================
// Kernel 2: GEMM  h = [y|x] @ Wcat^T + rs*Vb + Ub   (bf16x3, HMMA, ldmatrix)
// EXACT R7 winner: BM=128,BN=128,BK=32, 256 thr, 2-stage cp.async (WAIT1,
// 2-chunk lookahead), 2 CTAs/SM, fused BN-stat epilogue.
// ============================================================================
#define LDA        40
#define TILE_B     (128 * LDA)
#define STAGE_E    (4 * TILE_B)
#define STAGE_BYTES (STAGE_E * 2)          // 40960
#define SMEM2_BYTES (2 * STAGE_BYTES)      // 81920

__device__ __forceinline__ void issue_chunk(uint32_t sbase, int mrow0, int n0,
                                            int kc, int arow, int acol) {
    const size_t ga = (size_t)(mrow0 + arow) * KDIM + kc * 32 + acol;
    const size_t gw = (size_t)(n0 + arow) * KDIM + kc * 32 + acol;
    const uint32_t off = (uint32_t)(arow * LDA + acol) * 2;
    cp_async16(sbase + off,                     g_ahi + ga);
    cp_async16(sbase + off + 16,                g_ahi + ga + 8);
    cp_async16(sbase + TILE_B * 2 + off,        g_alo + ga);
    cp_async16(sbase + TILE_B * 2 + off + 16,   g_alo + ga + 8);
    cp_async16(sbase + 2 * TILE_B * 2 + off,      g_whi + gw);
    cp_async16(sbase + 2 * TILE_B * 2 + off + 16, g_whi + gw + 8);
    cp_async16(sbase + 3 * TILE_B * 2 + off,      g_wlo + gw);
    cp_async16(sbase + 3 * TILE_B * 2 + off + 16, g_wlo + gw + 8);
}

__global__ __launch_bounds__(256, 2) void k_gemm(const float* __restrict__ Vb,
                                                 const float* __restrict__ Ub) {
    extern __shared__ __align__(128) __nv_bfloat16 sm[];
    __shared__ float sBias[256];
    __shared__ float sred[24];

    const int tid  = threadIdx.x;
    const int wid  = tid >> 5;
    const int lane = tid & 31;

    const int ntile = blockIdx.x & 3;
    const int mtile = blockIdx.x >> 2;
    const int mrow0 = mtile * 128;
    const int n0    = ntile * 128;

    const int wm = (wid & 3) * 32;
    const int wn = (wid >> 2) * 64;

    for (int i = tid; i < 128; i += 256) {
        sBias[i]       = Vb[n0 + i];
        sBias[128 + i] = Ub[n0 + i];
    }
    if (tid < 24) sred[tid] = 0.f;

    float acc[2][8][4];
    #pragma unroll
    for (int mi = 0; mi < 2; mi++)
        #pragma unroll
        for (int nb = 0; nb < 8; nb++)
            #pragma unroll
            for (int q = 0; q < 4; q++) acc[mi][nb][q] = 0.f;

    const int arow = tid >> 1;
    const int acol = (tid & 1) * 16;
    const uint32_t sm_addr = smem_u32(sm);

    issue_chunk(sm_addr, mrow0, n0, 0, arow, acol);
    CP_COMMIT();
    issue_chunk(sm_addr + STAGE_BYTES, mrow0, n0, 1, arow, acol);
    CP_COMMIT();

    #pragma unroll 1
    for (int kc = 0; kc < 32; kc++) {
        CP_WAIT1();
        __syncthreads();

        {
            const uint32_t sA_hi = sm_addr + (uint32_t)(kc & 1) * STAGE_BYTES;
            const uint32_t sA_lo = sA_hi + TILE_B * 2;
            const uint32_t sB_hi = sA_hi + 2 * TILE_B * 2;
            const uint32_t sB_lo = sA_hi + 3 * TILE_B * 2;

            #pragma unroll
            for (int ks = 0; ks < 2; ks++) {
                const int k0 = ks * 16;
                uint32_t aH[2][4], aL[2][4];
                const int afr = lane & 15;
                const int afc = k0 + (lane >> 4) * 8;
                #pragma unroll
                for (int mi = 0; mi < 2; mi++) {
                    uint32_t ad = (uint32_t)((wm + mi * 16 + afr) * LDA + afc) * 2;
                    ldsm_x4(aH[mi], sA_hi + ad);
                    ldsm_x4(aL[mi], sA_lo + ad);
                }
                #pragma unroll
                for (int g = 0; g < 2; g++) {
                    uint32_t bH[4][2], bL[4][2];
                    #pragma unroll
                    for (int nq = 0; nq < 4; nq++) {
                        const int nb = g * 4 + nq;
                        const int brow = wn + nb * 8 + (lane & 7);
                        const int bcol = k0 + ((lane >> 3) & 1) * 8;
                        uint32_t bd = (uint32_t)(brow * LDA + bcol) * 2;
                        ldsm_x2(bH[nq], sB_hi + bd);
                        ldsm_x2(bL[nq], sB_lo + bd);
                    }
                    #pragma unroll
                    for (int nq = 0; nq < 4; nq++)
                        #pragma unroll
                        for (int mi = 0; mi < 2; mi++)
                            mma_bf16(acc[mi][g * 4 + nq], aH[mi], bH[nq]);
                    #pragma unroll
                    for (int nq = 0; nq < 4; nq++)
                        #pragma unroll
                        for (int mi = 0; mi < 2; mi++)
                            mma_bf16(acc[mi][g * 4 + nq], aL[mi], bH[nq]);
                    #pragma unroll
                    for (int nq = 0; nq < 4; nq++)
                        #pragma unroll
                        for (int mi = 0; mi < 2; mi++)
                            mma_bf16(acc[mi][g * 4 + nq], aH[mi], bL[nq]);
                }
            }
        }
        __syncthreads();

        const int kn = kc + 2;
        if (kn < 32)
            issue_chunk(sm_addr + (uint32_t)(kc & 1) * STAGE_BYTES, mrow0, n0, kn, arow, acol);
        CP_COMMIT();
    }

    // ---- epilogue: bias + write h + fused BN stats ----
    const int l4 = lane >> 2;
    const int lc = (lane & 3) * 2;

    #pragma unroll
    for (int mi = 0; mi < 2; mi++) {
        #pragma unroll
        for (int rr = 0; rr < 2; rr++) {
            const int row = wm + mi * 16 + rr * 8 + l4;
            const size_t grow = (size_t)mrow0 + row;
            const float rsv = g_rs[grow];
            float* hrow = g_h + grow * CDIM + n0;
            float lsum = 0.f, lsq = 0.f;
            #pragma unroll
            for (int nb = 0; nb < 8; nb++) {
                const int c = wn + nb * 8 + lc;
                float v0 = acc[mi][nb][rr * 2 + 0] + rsv * sBias[c]     + sBias[128 + c];
                float v1 = acc[mi][nb][rr * 2 + 1] + rsv * sBias[c + 1] + sBias[128 + c + 1];
                lsum += v0 + v1;
                lsq  += v0 * v0 + v1 * v1;
                *reinterpret_cast<float2*>(hrow + c) = make_float2(v0, v1);
            }
            lsum += __shfl_xor_sync(0xFFFFFFFF, lsum, 1);
            lsq  += __shfl_xor_sync(0xFFFFFFFF, lsq, 1);
            lsum += __shfl_xor_sync(0xFFFFFFFF, lsum, 2);
            lsq  += __shfl_xor_sync(0xFFFFFFFF, lsq, 2);
            if ((lane & 3) == 0) {
                int node = (int)(grow % NNODE);
                atomicAdd(&sred[node], lsum);
                atomicAdd(&sred[12 + node], lsq);
            }
        }
    }
    __syncthreads();
    if (tid < NNODE) {
        atomicAdd(&g_sum[tid], sred[tid]);
        atomicAdd(&g_sumsq[tid], sred[12 + tid]);
    }
}

// ============================================================================
// Kernel 3: finalize BN stats
// ============================================================================
__global__ void k_finalize(const float* __restrict__ gamma, const float* __restrict__ beta) {
    int t = threadIdx.x;
    if (t < NNODE) {
        const float inv_n = 1.0f / ((float)NB * (float)CDIM);
        float mean = g_sum[t] * inv_n;
        float var  = g_sumsq[t] * inv_n - mean * mean;
        var = fmaxf(var, 0.f);
        float sc = gamma[t] * rsqrtf(var + BN_EPS);
        g_scale[t] = sc;
        g_shift[t] = beta[t] - mean * sc;
    }
}

// ============================================================================
// Kernel 4: out = relu(x + h*scale + shift)   (2 float4 per thread)
// ============================================================================
__global__ __launch_bounds__(512) void k_output(const float* __restrict__ x,
                                                float* __restrict__ out) {
    const size_t base = (size_t)blockIdx.x * 1024 + threadIdx.x;
    #pragma unroll
    for (int r = 0; r < 2; r++) {
        size_t idx = base + r * 512;
        const float4 xv = reinterpret_cast<const float4*>(x)[idx];
        const float4 hv = reinterpret_cast<const float4*>(g_h)[idx];
        int node = (int)((idx >> 7) % NNODE);
        float sc = g_scale[node], sh = g_shift[node];
        float4 o;
        o.x = fmaxf(fmaf(hv.x, sc, sh) + xv.x, 0.f);
        o.y = fmaxf(fmaf(hv.y, sc, sh) + xv.y, 0.f);
        o.z = fmaxf(fmaf(hv.z, sc, sh) + xv.z, 0.f);
        o.w = fmaxf(fmaf(hv.w, sc, sh) + xv.w, 0.f);
        reinterpret_cast<float4*>(out)[idx] = o;
    }
}

// ============================================================================
// Launch
// ============================================================================
extern "C" void kernel_launch(void* const* d_in, const int* in_sizes, int n_in,
                              void* d_out, int out_size) {
    const float* x     = (const float*)d_in[0];
    const float* Uw    = (const float*)d_in[1];
    const float* Ub    = (const float*)d_in[2];
    const float* Vw    = (const float*)d_in[3];
    const float* Vb    = (const float*)d_in[4];
    const float* gamma = (const float*)d_in[5];
    const float* beta  = (const float*)d_in[6];
    float* out = (float*)d_out;

    cudaFuncSetAttribute(k_gemm, cudaFuncAttributeMaxDynamicSharedMemorySize, SMEM2_BYTES);

    k_zero_stats<<<1, 32>>>();
    k_prep_w<<<(NDIM * KDIM + 255) / 256, 256>>>(Uw, Vw);
    k_adjacency<<<NB, 128>>>(x);
    k_gemm<<<(ROWS / 128) * 4, 256, SMEM2_BYTES>>>(Vb, Ub);
    k_finalize<<<1, 32>>>(gamma, beta);
    k_output<<<(unsigned)((size_t)ROWS * CDIM / 4 / 1024), 512>>>(x, out);
}